// round 1
// baseline (speedup 1.0000x reference)
#include <cuda_runtime.h>

// ---------------- sizes / offsets ----------------
static const size_t C1_PER = 32ull * 32 * 256 * 256;   // 67,108,864 (per image)
static const size_t C2_PER = 32ull * 64 * 128 * 128;   // 33,554,432 (per image)

#define OFF_PRED 0
#define OFF_ZT   64
#define OFF_ZT1  (64 + 32*128*64*64)                    // 16,777,280
#define OFF_CORR (OFF_ZT1 + 32*128*64*64)               // 33,554,496
#define OFF_HT   (OFF_CORR + 32*169*64*64)              // 55,705,664

// ---------------- scratch (no runtime allocs allowed) ----------------
__device__ float g_c1[2ull * 32 * 32 * 256 * 256];      // 536 MB
__device__ float g_c2[2ull * 32 * 64 * 128 * 128];      // 268 MB

// ---------------- conv1: 3->32, 256x256, stride 1, pad 1, ReLU ----------------
// grid (8,16,64) block (16,16). Thread computes pixels (y,x) and (y,x+16), all 32 oc.
__global__ void conv1_kernel(const float* __restrict__ imgA,
                             const float* __restrict__ imgB,
                             const float* __restrict__ w1,
                             const float* __restrict__ b1) {
    __shared__ float ws[864];
    __shared__ float bs[32];
    int t = threadIdx.y * 16 + threadIdx.x;
    for (int i = t; i < 864; i += 256) ws[i] = w1[i];
    if (t < 32) bs[t] = b1[t];
    __syncthreads();

    int img = blockIdx.z >> 5;
    int b   = blockIdx.z & 31;
    const float* src = (img == 0 ? imgA : imgB) + (size_t)b * 3 * 256 * 256;
    float* dst = g_c1 + (size_t)img * C1_PER + (size_t)b * 32 * 256 * 256;

    int y  = blockIdx.y * 16 + threadIdx.y;
    int x0 = blockIdx.x * 32 + threadIdx.x;
    int x1 = x0 + 16;

    float in0[27], in1[27];
    #pragma unroll
    for (int c = 0; c < 3; c++)
        #pragma unroll
        for (int r = 0; r < 3; r++)
            #pragma unroll
            for (int s = 0; s < 3; s++) {
                int iy = y + r - 1;
                int ixa = x0 + s - 1;
                int ixb = x1 + s - 1;
                bool vy = (iy >= 0) && (iy < 256);
                const float* p = src + ((size_t)c * 256 + iy) * 256;
                int k = c * 9 + r * 3 + s;
                in0[k] = (vy && ixa >= 0 && ixa < 256) ? p[ixa] : 0.f;
                in1[k] = (vy && ixb < 256)             ? p[ixb] : 0.f;  // ixb >= 15 always
            }

    for (int oc = 0; oc < 32; oc++) {
        float a0 = bs[oc];
        float a1 = a0;
        #pragma unroll
        for (int k = 0; k < 27; k++) {
            float w = ws[oc * 27 + k];
            a0 += in0[k] * w;
            a1 += in1[k] * w;
        }
        float* q = dst + ((size_t)oc * 256 + y) * 256;
        q[x0] = fmaxf(a0, 0.f);
        q[x1] = fmaxf(a1, 0.f);
    }
}

// ---------------- conv2: 32->64, out 128x128, stride 2, pad 1, ReLU ----------------
// grid (8,8,64) block 256. Tile 16x16 outputs. Thread: 4 pixels x 16 oc.
__global__ void __launch_bounds__(256, 2)
conv2_kernel(const float* __restrict__ w2, const float* __restrict__ b2) {
    __shared__ float tile[33 * 33];
    __shared__ float wsm[64 * 9];
    int t = threadIdx.x;
    int img = blockIdx.z >> 5, b = blockIdx.z & 31;
    const float* src = g_c1 + (size_t)img * C1_PER + (size_t)b * 32 * 256 * 256;
    float* dst = g_c2 + (size_t)img * C2_PER + (size_t)b * 64 * 128 * 128;

    int oy0 = blockIdx.y * 16, ox0 = blockIdx.x * 16;
    int iy0 = oy0 * 2 - 1, ix0 = ox0 * 2 - 1;

    int ocs = t >> 6;            // 0..3 -> oc base ocs*16 (constant per warp -> broadcast LDS)
    int ps  = t & 63;
    int py  = ps >> 3, px = ps & 7;

    float acc[4][16];
    #pragma unroll
    for (int a = 0; a < 4; a++)
        #pragma unroll
        for (int j = 0; j < 16; j++) acc[a][j] = 0.f;

    for (int ic = 0; ic < 32; ic++) {
        __syncthreads();
        for (int i = t; i < 33 * 33; i += 256) {
            int ry = i / 33, rx = i % 33;
            int iy = iy0 + ry, ix = ix0 + rx;
            tile[i] = (iy >= 0 && iy < 256 && ix >= 0 && ix < 256)
                      ? src[((size_t)ic * 256 + iy) * 256 + ix] : 0.f;
        }
        for (int i = t; i < 576; i += 256) {
            int oc = i / 9, k = i % 9;
            wsm[i] = w2[(size_t)oc * 288 + (size_t)ic * 9 + k];   // OIHW
        }
        __syncthreads();

        #pragma unroll
        for (int r = 0; r < 3; r++)
            #pragma unroll
            for (int s = 0; s < 3; s++) {
                float w[16];
                #pragma unroll
                for (int j = 0; j < 16; j++) w[j] = wsm[(ocs * 16 + j) * 9 + r * 3 + s];
                #pragma unroll
                for (int aa = 0; aa < 2; aa++)
                    #pragma unroll
                    for (int bb = 0; bb < 2; bb++) {
                        float v = tile[((py + 8 * aa) * 2 + r) * 33 + (px + 8 * bb) * 2 + s];
                        int a = aa * 2 + bb;
                        #pragma unroll
                        for (int j = 0; j < 16; j++) acc[a][j] += v * w[j];
                    }
            }
    }

    int oc0 = ocs * 16;
    #pragma unroll
    for (int aa = 0; aa < 2; aa++)
        #pragma unroll
        for (int bb = 0; bb < 2; bb++) {
            int oy = oy0 + py + 8 * aa;
            int ox = ox0 + px + 8 * bb;
            #pragma unroll
            for (int j = 0; j < 16; j++) {
                float v = acc[aa * 2 + bb][j] + b2[oc0 + j];
                dst[((size_t)(oc0 + j) * 128 + oy) * 128 + ox] = fmaxf(v, 0.f);
            }
        }
}

// ---------------- conv3: 64->128, out 64x64, stride 2, pad 1, ReLU -> d_out ----------------
// grid (4,8,64) block 256. Tile 8x16 outputs. Thread: 4 pixels x 16 oc.
__global__ void __launch_bounds__(256, 2)
conv3_kernel(const float* __restrict__ w3, const float* __restrict__ b3,
             float* __restrict__ out_all) {
    __shared__ float tile[17 * 33];
    __shared__ float wsm[128 * 9];
    int t = threadIdx.x;
    int img = blockIdx.z >> 5, b = blockIdx.z & 31;
    const float* src = g_c2 + (size_t)img * C2_PER + (size_t)b * 64 * 128 * 128;
    float* dst = out_all + (img == 0 ? OFF_ZT : OFF_ZT1) + (size_t)b * 128 * 64 * 64;

    int oy0 = blockIdx.y * 8, ox0 = blockIdx.x * 16;
    int iy0 = oy0 * 2 - 1, ix0 = ox0 * 2 - 1;

    int ocs = t >> 5;            // 0..7 -> oc base ocs*16 (constant per warp)
    int ps  = t & 31;
    int py  = ps >> 2, px = ps & 3;   // pixels (py, px + 4*bb)

    float acc[4][16];
    #pragma unroll
    for (int a = 0; a < 4; a++)
        #pragma unroll
        for (int j = 0; j < 16; j++) acc[a][j] = 0.f;

    for (int ic = 0; ic < 64; ic++) {
        __syncthreads();
        for (int i = t; i < 17 * 33; i += 256) {
            int ry = i / 33, rx = i % 33;
            int iy = iy0 + ry, ix = ix0 + rx;
            tile[i] = (iy >= 0 && iy < 128 && ix >= 0 && ix < 128)
                      ? src[((size_t)ic * 128 + iy) * 128 + ix] : 0.f;
        }
        for (int i = t; i < 1152; i += 256) {
            int oc = i / 9, k = i % 9;
            wsm[i] = w3[(size_t)oc * 576 + (size_t)ic * 9 + k];   // OIHW
        }
        __syncthreads();

        #pragma unroll
        for (int r = 0; r < 3; r++)
            #pragma unroll
            for (int s = 0; s < 3; s++) {
                float w[16];
                #pragma unroll
                for (int j = 0; j < 16; j++) w[j] = wsm[(ocs * 16 + j) * 9 + r * 3 + s];
                #pragma unroll
                for (int bb = 0; bb < 4; bb++) {
                    float v = tile[(py * 2 + r) * 33 + (px + 4 * bb) * 2 + s];
                    #pragma unroll
                    for (int j = 0; j < 16; j++) acc[bb][j] += v * w[j];
                }
            }
    }

    int oc0 = ocs * 16;
    int oy = oy0 + py;
    #pragma unroll
    for (int bb = 0; bb < 4; bb++) {
        int ox = ox0 + px + 4 * bb;
        #pragma unroll
        for (int j = 0; j < 16; j++) {
            float v = acc[bb][j] + b3[oc0 + j];
            dst[((size_t)(oc0 + j) * 64 + oy) * 64 + ox] = fmaxf(v, 0.f);
        }
    }
}

// ---------------- corr: 169-offset channel correlation ----------------
// grid (4,4,32) block 256, one thread per pixel of a 16x16 tile; accumulators in smem.
__global__ void __launch_bounds__(256, 1)
corr_kernel(float* __restrict__ out_all) {
    extern __shared__ float sm[];
    float* accs = sm;                    // [169][256]
    float* ztt  = sm + 169 * 256;        // [8][16][16]
    float* z1t  = ztt + 2048;            // [8][28][28]

    int t = threadIdx.x;
    int b = blockIdx.z;
    int gy0 = blockIdx.y * 16, gx0 = blockIdx.x * 16;
    const float* zt  = out_all + OFF_ZT  + (size_t)b * 128 * 4096;
    const float* zt1 = out_all + OFF_ZT1 + (size_t)b * 128 * 4096;

    for (int i = t; i < 169 * 256; i += 256) accs[i] = 0.f;

    int ty = t >> 4, tx = t & 15;

    for (int cc = 0; cc < 16; cc++) {
        __syncthreads();
        #pragma unroll
        for (int k = 0; k < 8; k++) {
            int i = t + k * 256;
            int c = i >> 8, rem = i & 255;
            ztt[i] = zt[((size_t)(cc * 8 + c)) * 4096 + (gy0 + (rem >> 4)) * 64 + gx0 + (rem & 15)];
        }
        for (int i = t; i < 8 * 784; i += 256) {
            int c = i / 784, rem = i % 784;
            int yy = rem / 28, xx = rem % 28;
            int gy = gy0 - 6 + yy, gx = gx0 - 6 + xx;
            z1t[i] = (gy >= 0 && gy < 64 && gx >= 0 && gx < 64)
                     ? zt1[((size_t)(cc * 8 + c)) * 4096 + gy * 64 + gx] : 0.f;
        }
        __syncthreads();

        float zr[8];
        #pragma unroll
        for (int c = 0; c < 8; c++) zr[c] = ztt[c * 256 + t];

        for (int di = 0; di < 13; di++) {
            const float* row  = z1t + (ty + di) * 28 + tx;
            float*       arow = accs + di * 13 * 256 + t;
            #pragma unroll
            for (int dj = 0; dj < 13; dj++) {
                float p = 0.f;
                #pragma unroll
                for (int c = 0; c < 8; c++) p += zr[c] * row[c * 784 + dj];
                arow[dj * 256] += p;
            }
        }
    }

    const float inv = 0.0883883476483184f;   // 1/sqrt(128)
    float* co = out_all + OFF_CORR + (size_t)b * 169 * 4096;
    int gy = gy0 + ty, gx = gx0 + tx;
    for (int o = 0; o < 169; o++)
        co[(size_t)o * 4096 + gy * 64 + gx] = accs[o * 256 + t] * inv;
}

// ---------------- h_t: spatial mean of corr ----------------
__global__ void ht_kernel(float* __restrict__ out_all) {
    int o = blockIdx.x, b = blockIdx.y;
    const float* co = out_all + OFF_CORR + ((size_t)b * 169 + o) * 4096;
    float s = 0.f;
    for (int i = threadIdx.x; i < 4096; i += 256) s += co[i];
    __shared__ float red[8];
    #pragma unroll
    for (int off = 16; off; off >>= 1) s += __shfl_down_sync(0xffffffffu, s, off);
    if ((threadIdx.x & 31) == 0) red[threadIdx.x >> 5] = s;
    __syncthreads();
    if (threadIdx.x < 8) {
        s = red[threadIdx.x];
        #pragma unroll
        for (int off = 4; off; off >>= 1) s += __shfl_down_sync(0xffu, s, off);
        if (threadIdx.x == 0) out_all[OFF_HT + b * 169 + o] = s * (1.f / 4096.f);
    }
}

// ---------------- head: pred = h_t @ w_head^T + b_head ----------------
__global__ void head_kernel(float* __restrict__ out_all,
                            const float* __restrict__ wh,
                            const float* __restrict__ bh) {
    int t = threadIdx.x;
    if (t >= 64) return;
    int b = t >> 1, j = t & 1;
    const float* h = out_all + OFF_HT + b * 169;
    float s = bh[j];
    for (int o = 0; o < 169; o++) s += h[o] * wh[j * 169 + o];
    out_all[OFF_PRED + b * 2 + j] = s;
}

// ---------------- launch ----------------
extern "C" void kernel_launch(void* const* d_in, const int* in_sizes, int n_in,
                              void* d_out, int out_size) {
    const float* img_t  = (const float*)d_in[0];
    const float* img_t1 = (const float*)d_in[1];
    const float* w1 = (const float*)d_in[2];
    const float* b1 = (const float*)d_in[3];
    const float* w2 = (const float*)d_in[4];
    const float* b2 = (const float*)d_in[5];
    const float* w3 = (const float*)d_in[6];
    const float* b3 = (const float*)d_in[7];
    const float* wh = (const float*)d_in[8];
    const float* bh = (const float*)d_in[9];
    float* out = (float*)d_out;

    conv1_kernel<<<dim3(8, 16, 64), dim3(16, 16)>>>(img_t, img_t1, w1, b1);
    conv2_kernel<<<dim3(8, 8, 64), 256>>>(w2, b2);
    conv3_kernel<<<dim3(4, 8, 64), 256>>>(w3, b3, out);

    int corr_smem = (169 * 256 + 2048 + 8 * 784) * 4;   // 206,336 B
    cudaFuncSetAttribute(corr_kernel, cudaFuncAttributeMaxDynamicSharedMemorySize, corr_smem);
    corr_kernel<<<dim3(4, 4, 32), 256, corr_smem>>>(out);

    ht_kernel<<<dim3(169, 32), 256>>>(out);
    head_kernel<<<1, 64>>>(out, wh, bh);
}

// round 9
// speedup vs baseline: 1.2744x; 1.2744x over previous
#include <cuda_runtime.h>

// ---------------- sizes / offsets ----------------
static const size_t C1_PER = 32ull * 32 * 256 * 256;
static const size_t C2_PER = 32ull * 64 * 128 * 128;

#define OFF_PRED 0
#define OFF_ZT   64
#define OFF_ZT1  (64 + 32*128*64*64)
#define OFF_CORR (OFF_ZT1 + 32*128*64*64)
#define OFF_HT   (OFF_CORR + 32*169*64*64)

// ---------------- scratch ----------------
__device__ float g_c1[2ull * 32 * 32 * 256 * 256];
__device__ float g_c2[2ull * 32 * 64 * 128 * 128];

// ---------------- f32x2 helpers ----------------
typedef unsigned long long ull;
__device__ __forceinline__ ull fma2(ull a, ull b, ull c) {
    ull d;
    asm("fma.rn.f32x2 %0, %1, %2, %3;" : "=l"(d) : "l"(a), "l"(b), "l"(c));
    return d;
}
__device__ __forceinline__ ull packff(float lo, float hi) {
    ull d;
    asm("mov.b64 %0, {%1, %2};" : "=l"(d) : "f"(lo), "f"(hi));
    return d;
}
__device__ __forceinline__ float2 unpack2(ull v) {
    float2 f;
    asm("mov.b64 {%0, %1}, %2;" : "=f"(f.x), "=f"(f.y) : "l"(v));
    return f;
}

// ---------------- conv1: 3->32, 256x256, s1, p1, ReLU ----------------
// grid (8,16,64) block (16,16). Thread: 2 pixels x 32 oc (16 oc-pairs, f32x2).
__global__ void conv1_kernel(const float* __restrict__ imgA,
                             const float* __restrict__ imgB,
                             const float* __restrict__ w1,
                             const float* __restrict__ b1) {
    __shared__ __align__(16) float ws[27 * 32 + 4];   // [k][oc], padded even
    __shared__ __align__(16) float bs[32];
    int t = threadIdx.y * 16 + threadIdx.x;
    for (int i = t; i < 864; i += 256) {
        int k = i >> 5, oc = i & 31;
        ws[i] = w1[oc * 27 + k];
    }
    if (t < 32) bs[t] = b1[t];
    __syncthreads();

    int img = blockIdx.z >> 5;
    int b   = blockIdx.z & 31;
    const float* src = (img == 0 ? imgA : imgB) + (size_t)b * 3 * 256 * 256;
    float* dst = g_c1 + (size_t)img * C1_PER + (size_t)b * 32 * 256 * 256;

    int y  = blockIdx.y * 16 + threadIdx.y;
    int x0 = blockIdx.x * 32 + threadIdx.x;
    int x1 = x0 + 16;

    float in0[27], in1[27];
    #pragma unroll
    for (int c = 0; c < 3; c++)
        #pragma unroll
        for (int r = 0; r < 3; r++)
            #pragma unroll
            for (int s = 0; s < 3; s++) {
                int iy = y + r - 1;
                int ixa = x0 + s - 1;
                int ixb = x1 + s - 1;
                bool vy = (iy >= 0) && (iy < 256);
                const float* p = src + ((size_t)c * 256 + iy) * 256;
                int k = c * 9 + r * 3 + s;
                in0[k] = (vy && ixa >= 0 && ixa < 256) ? p[ixa] : 0.f;
                in1[k] = (vy && ixb < 256)             ? p[ixb] : 0.f;
            }

    ull acc0[16], acc1[16];
    #pragma unroll
    for (int jp = 0; jp < 16; jp++) {
        ull bb = *(const ull*)&bs[jp * 2];
        acc0[jp] = bb; acc1[jp] = bb;
    }

    #pragma unroll
    for (int k = 0; k < 27; k++) {
        ull v0 = packff(in0[k], in0[k]);
        ull v1 = packff(in1[k], in1[k]);
        #pragma unroll
        for (int jp = 0; jp < 16; jp++) {
            ull W = *(const ull*)&ws[k * 32 + jp * 2];
            acc0[jp] = fma2(v0, W, acc0[jp]);
            acc1[jp] = fma2(v1, W, acc1[jp]);
        }
    }

    #pragma unroll
    for (int jp = 0; jp < 16; jp++) {
        float2 f0 = unpack2(acc0[jp]);
        float2 f1 = unpack2(acc1[jp]);
        float* qa = dst + ((size_t)(jp * 2)     * 256 + y) * 256;
        float* qb = dst + ((size_t)(jp * 2 + 1) * 256 + y) * 256;
        qa[x0] = fmaxf(f0.x, 0.f);
        qb[x0] = fmaxf(f0.y, 0.f);
        qa[x1] = fmaxf(f1.x, 0.f);
        qb[x1] = fmaxf(f1.y, 0.f);
    }
}

// ---------------- conv2: 32->64, out 128x128, s2, p1, ReLU ----------------
// grid (8,8,64) block 256. Thread: 4 pixels x 16 oc (8 oc-pairs f32x2).
__global__ void __launch_bounds__(256, 2)
conv2_kernel(const float* __restrict__ w2, const float* __restrict__ b2) {
    __shared__ __align__(16) float wsm[9 * 64];       // [k][oc] -- declared FIRST, 16B aligned
    __shared__ __align__(16) float tile[33 * 33 + 3]; // padded to multiple of 4
    int t = threadIdx.x;
    int img = blockIdx.z >> 5, b = blockIdx.z & 31;
    const float* src = g_c1 + (size_t)img * C1_PER + (size_t)b * 32 * 256 * 256;
    float* dst = g_c2 + (size_t)img * C2_PER + (size_t)b * 64 * 128 * 128;

    int oy0 = blockIdx.y * 16, ox0 = blockIdx.x * 16;
    int iy0 = oy0 * 2 - 1, ix0 = ox0 * 2 - 1;

    int ocs = t >> 6;                 // warp-uniform oc group
    int ps  = t & 63;
    int py  = ps >> 3, px = ps & 7;
    int oc0 = ocs * 16;

    ull acc[4][8];
    #pragma unroll
    for (int jp = 0; jp < 8; jp++) {
        ull bb = packff(b2[oc0 + jp * 2], b2[oc0 + jp * 2 + 1]);
        #pragma unroll
        for (int a = 0; a < 4; a++) acc[a][jp] = bb;
    }

    for (int ic = 0; ic < 32; ic++) {
        __syncthreads();
        for (int i = t; i < 33 * 33; i += 256) {
            int ry = i / 33, rx = i % 33;
            int iy = iy0 + ry, ix = ix0 + rx;
            tile[i] = (iy >= 0 && iy < 256 && ix >= 0 && ix < 256)
                      ? src[((size_t)ic * 256 + iy) * 256 + ix] : 0.f;
        }
        for (int i = t; i < 576; i += 256) {
            int k = i >> 6, oc = i & 63;
            wsm[i] = w2[(size_t)oc * 288 + (size_t)ic * 9 + k];
        }
        __syncthreads();

        #pragma unroll
        for (int r = 0; r < 3; r++)
            #pragma unroll
            for (int s = 0; s < 3; s++) {
                int k = r * 3 + s;
                ull W[8];
                #pragma unroll
                for (int jp = 0; jp < 8; jp++)
                    W[jp] = *(const ull*)&wsm[k * 64 + oc0 + jp * 2];
                #pragma unroll
                for (int aa = 0; aa < 2; aa++)
                    #pragma unroll
                    for (int bb2_ = 0; bb2_ < 2; bb2_++) {
                        float v = tile[((py + 8 * aa) * 2 + r) * 33 + (px + 8 * bb2_) * 2 + s];
                        ull vv = packff(v, v);
                        int a = aa * 2 + bb2_;
                        #pragma unroll
                        for (int jp = 0; jp < 8; jp++)
                            acc[a][jp] = fma2(vv, W[jp], acc[a][jp]);
                    }
            }
    }

    #pragma unroll
    for (int aa = 0; aa < 2; aa++)
        #pragma unroll
        for (int bb2_ = 0; bb2_ < 2; bb2_++) {
            int oy = oy0 + py + 8 * aa;
            int ox = ox0 + px + 8 * bb2_;
            int a = aa * 2 + bb2_;
            #pragma unroll
            for (int jp = 0; jp < 8; jp++) {
                float2 f = unpack2(acc[a][jp]);
                dst[((size_t)(oc0 + jp * 2)     * 128 + oy) * 128 + ox] = fmaxf(f.x, 0.f);
                dst[((size_t)(oc0 + jp * 2 + 1) * 128 + oy) * 128 + ox] = fmaxf(f.y, 0.f);
            }
        }
}

// ---------------- conv3: 64->128, out 64x64, s2, p1, ReLU -> d_out ----------------
// grid (4,8,64) block 256. Thread: 4 pixels x 16 oc (8 oc-pairs f32x2).
__global__ void __launch_bounds__(256, 2)
conv3_kernel(const float* __restrict__ w3, const float* __restrict__ b3,
             float* __restrict__ out_all) {
    __shared__ __align__(16) float wsm[9 * 128];      // [k][oc] -- declared FIRST, 16B aligned
    __shared__ __align__(16) float tile[17 * 33 + 3]; // padded to multiple of 4
    int t = threadIdx.x;
    int img = blockIdx.z >> 5, b = blockIdx.z & 31;
    const float* src = g_c2 + (size_t)img * C2_PER + (size_t)b * 64 * 128 * 128;
    float* dst = out_all + (img == 0 ? OFF_ZT : OFF_ZT1) + (size_t)b * 128 * 64 * 64;

    int oy0 = blockIdx.y * 8, ox0 = blockIdx.x * 16;
    int iy0 = oy0 * 2 - 1, ix0 = ox0 * 2 - 1;

    int ocs = t >> 5;                 // warp-uniform oc group
    int ps  = t & 31;
    int py  = ps >> 2, px = ps & 3;
    int oc0 = ocs * 16;

    ull acc[4][8];
    #pragma unroll
    for (int jp = 0; jp < 8; jp++) {
        ull bb = packff(b3[oc0 + jp * 2], b3[oc0 + jp * 2 + 1]);
        #pragma unroll
        for (int a = 0; a < 4; a++) acc[a][jp] = bb;
    }

    for (int ic = 0; ic < 64; ic++) {
        __syncthreads();
        for (int i = t; i < 17 * 33; i += 256) {
            int ry = i / 33, rx = i % 33;
            int iy = iy0 + ry, ix = ix0 + rx;
            tile[i] = (iy >= 0 && iy < 128 && ix >= 0 && ix < 128)
                      ? src[((size_t)ic * 128 + iy) * 128 + ix] : 0.f;
        }
        for (int i = t; i < 1152; i += 256) {
            int k = i >> 7, oc = i & 127;
            wsm[i] = w3[(size_t)oc * 576 + (size_t)ic * 9 + k];
        }
        __syncthreads();

        #pragma unroll
        for (int r = 0; r < 3; r++)
            #pragma unroll
            for (int s = 0; s < 3; s++) {
                int k = r * 3 + s;
                ull W[8];
                #pragma unroll
                for (int jp = 0; jp < 8; jp++)
                    W[jp] = *(const ull*)&wsm[k * 128 + oc0 + jp * 2];
                #pragma unroll
                for (int bb3 = 0; bb3 < 4; bb3++) {
                    float v = tile[(py * 2 + r) * 33 + (px + 4 * bb3) * 2 + s];
                    ull vv = packff(v, v);
                    #pragma unroll
                    for (int jp = 0; jp < 8; jp++)
                        acc[bb3][jp] = fma2(vv, W[jp], acc[bb3][jp]);
                }
            }
    }

    int oy = oy0 + py;
    #pragma unroll
    for (int bb3 = 0; bb3 < 4; bb3++) {
        int ox = ox0 + px + 4 * bb3;
        #pragma unroll
        for (int jp = 0; jp < 8; jp++) {
            float2 f = unpack2(acc[bb3][jp]);
            dst[((size_t)(oc0 + jp * 2)     * 64 + oy) * 64 + ox] = fmaxf(f.x, 0.f);
            dst[((size_t)(oc0 + jp * 2 + 1) * 64 + oy) * 64 + ox] = fmaxf(f.y, 0.f);
        }
    }
}

// ---------------- corr: register-tiled, 4 px x 13 dj per thread, di split over 4 ----------------
// grid (4,4,32) block 256. smem acc [169][256] persists over channel chunks.
__global__ void __launch_bounds__(256, 1)
corr_kernel(float* __restrict__ out_all) {
    extern __shared__ __align__(16) float sm[];
    float* accs = sm;                    // [169][256]
    float* ztt  = sm + 169 * 256;        // [8][256]  ([c][pix])
    float* z1t  = ztt + 2048;            // [8][28][28]

    int t = threadIdx.x;
    int b = blockIdx.z;
    int gy0 = blockIdx.y * 16, gx0 = blockIdx.x * 16;
    const float* zt  = out_all + OFF_ZT  + (size_t)b * 128 * 4096;
    const float* zt1 = out_all + OFF_ZT1 + (size_t)b * 128 * 4096;

    for (int i = t; i < 169 * 256; i += 256) accs[i] = 0.f;

    int g   = t & 63;         // pixel group (warp-contiguous)
    int tdi = t >> 6;         // di sub-group (warp-uniform)
    int ty  = g >> 2;
    int gx4 = (g & 3) << 2;
    int ndis = (tdi == 0) ? 4 : 3;
    int dis[4] = {tdi, tdi + 4, tdi + 8, 12};

    for (int cc = 0; cc < 16; cc++) {
        __syncthreads();
        #pragma unroll
        for (int k = 0; k < 8; k++)
            ztt[k * 256 + t] = zt[((size_t)(cc * 8 + k)) * 4096 +
                                  (gy0 + (t >> 4)) * 64 + gx0 + (t & 15)];
        for (int i = t; i < 8 * 784; i += 256) {
            int c = i / 784, rem = i - c * 784;
            int yy = rem / 28, xx = rem - yy * 28;
            int gy = gy0 - 6 + yy, gx = gx0 - 6 + xx;
            z1t[i] = (gy >= 0 && gy < 64 && gx >= 0 && gx < 64)
                     ? zt1[((size_t)(cc * 8 + c)) * 4096 + gy * 64 + gx] : 0.f;
        }
        __syncthreads();

        for (int dd = 0; dd < ndis; dd++) {
            int di = dis[dd];
            float p[13][4];
            #pragma unroll
            for (int dj = 0; dj < 13; dj++)
                #pragma unroll
                for (int q = 0; q < 4; q++) p[dj][q] = 0.f;

            #pragma unroll
            for (int c = 0; c < 8; c++) {
                float4 z4 = *(const float4*)&ztt[c * 256 + g * 4];
                const float* rb = &z1t[c * 784 + (ty + di) * 28 + gx4];
                float4 r0 = *(const float4*)(rb);
                float4 r1 = *(const float4*)(rb + 4);
                float4 r2 = *(const float4*)(rb + 8);
                float4 r3 = *(const float4*)(rb + 12);
                float rv[16] = {r0.x, r0.y, r0.z, r0.w, r1.x, r1.y, r1.z, r1.w,
                                r2.x, r2.y, r2.z, r2.w, r3.x, r3.y, r3.z, r3.w};
                #pragma unroll
                for (int dj = 0; dj < 13; dj++) {
                    p[dj][0] += z4.x * rv[dj];
                    p[dj][1] += z4.y * rv[dj + 1];
                    p[dj][2] += z4.z * rv[dj + 2];
                    p[dj][3] += z4.w * rv[dj + 3];
                }
            }
            #pragma unroll
            for (int dj = 0; dj < 13; dj++) {
                float4* ap = (float4*)&accs[(di * 13 + dj) * 256 + g * 4];
                float4 av = *ap;
                av.x += p[dj][0]; av.y += p[dj][1];
                av.z += p[dj][2]; av.w += p[dj][3];
                *ap = av;
            }
        }
    }
    __syncthreads();

    const float inv = 0.0883883476483184f;   // 1/sqrt(128)
    float* co = out_all + OFF_CORR + (size_t)b * 169 * 4096;
    int gy = gy0 + (t >> 4), gx = gx0 + (t & 15);
    for (int o = 0; o < 169; o++)
        co[(size_t)o * 4096 + gy * 64 + gx] = accs[o * 256 + t] * inv;
}

// ---------------- h_t: spatial mean of corr ----------------
__global__ void ht_kernel(float* __restrict__ out_all) {
    int o = blockIdx.x, b = blockIdx.y;
    const float4* co = (const float4*)(out_all + OFF_CORR + ((size_t)b * 169 + o) * 4096);
    float s = 0.f;
    for (int i = threadIdx.x; i < 1024; i += 256) {
        float4 v = co[i];
        s += (v.x + v.y) + (v.z + v.w);
    }
    __shared__ float red[8];
    #pragma unroll
    for (int off = 16; off; off >>= 1) s += __shfl_down_sync(0xffffffffu, s, off);
    if ((threadIdx.x & 31) == 0) red[threadIdx.x >> 5] = s;
    __syncthreads();
    if (threadIdx.x < 8) {
        s = red[threadIdx.x];
        #pragma unroll
        for (int off = 4; off; off >>= 1) s += __shfl_down_sync(0xffu, s, off);
        if (threadIdx.x == 0) out_all[OFF_HT + b * 169 + o] = s * (1.f / 4096.f);
    }
}

// ---------------- head ----------------
__global__ void head_kernel(float* __restrict__ out_all,
                            const float* __restrict__ wh,
                            const float* __restrict__ bh) {
    int t = threadIdx.x;
    if (t >= 64) return;
    int b = t >> 1, j = t & 1;
    const float* h = out_all + OFF_HT + b * 169;
    float s = bh[j];
    for (int o = 0; o < 169; o++) s += h[o] * wh[j * 169 + o];
    out_all[OFF_PRED + b * 2 + j] = s;
}

// ---------------- launch ----------------
extern "C" void kernel_launch(void* const* d_in, const int* in_sizes, int n_in,
                              void* d_out, int out_size) {
    const float* img_t  = (const float*)d_in[0];
    const float* img_t1 = (const float*)d_in[1];
    const float* w1 = (const float*)d_in[2];
    const float* b1 = (const float*)d_in[3];
    const float* w2 = (const float*)d_in[4];
    const float* b2 = (const float*)d_in[5];
    const float* w3 = (const float*)d_in[6];
    const float* b3 = (const float*)d_in[7];
    const float* wh = (const float*)d_in[8];
    const float* bh = (const float*)d_in[9];
    float* out = (float*)d_out;

    conv1_kernel<<<dim3(8, 16, 64), dim3(16, 16)>>>(img_t, img_t1, w1, b1);
    conv2_kernel<<<dim3(8, 8, 64), 256>>>(w2, b2);
    conv3_kernel<<<dim3(4, 8, 64), 256>>>(w3, b3, out);

    int corr_smem = (169 * 256 + 2048 + 8 * 784) * 4;   // 206,336 B
    cudaFuncSetAttribute(corr_kernel, cudaFuncAttributeMaxDynamicSharedMemorySize, corr_smem);
    corr_kernel<<<dim3(4, 4, 32), 256, corr_smem>>>(out);

    ht_kernel<<<dim3(169, 32), 256>>>(out);
    head_kernel<<<1, 64>>>(out, wh, bh);
}

// round 10
// speedup vs baseline: 1.2748x; 1.0003x over previous
#include <cuda_runtime.h>

// ---------------- sizes / offsets ----------------
static const size_t C1_PER = 32ull * 32 * 256 * 256;
static const size_t C2_PER = 32ull * 64 * 128 * 128;

#define OFF_PRED 0
#define OFF_ZT   64
#define OFF_ZT1  (64 + 32*128*64*64)
#define OFF_CORR (OFF_ZT1 + 32*128*64*64)
#define OFF_HT   (OFF_CORR + 32*169*64*64)

// ---------------- scratch ----------------
__device__ float g_c1[2ull * 32 * 32 * 256 * 256];
__device__ float g_c2[2ull * 32 * 64 * 128 * 128];

// ---------------- f32x2 helpers ----------------
typedef unsigned long long ull;
__device__ __forceinline__ ull fma2(ull a, ull b, ull c) {
    ull d;
    asm("fma.rn.f32x2 %0, %1, %2, %3;" : "=l"(d) : "l"(a), "l"(b), "l"(c));
    return d;
}
__device__ __forceinline__ ull packff(float lo, float hi) {
    ull d;
    asm("mov.b64 %0, {%1, %2};" : "=l"(d) : "f"(lo), "f"(hi));
    return d;
}
__device__ __forceinline__ float2 unpack2(ull v) {
    float2 f;
    asm("mov.b64 {%0, %1}, %2;" : "=f"(f.x), "=f"(f.y) : "l"(v));
    return f;
}

// ---------------- conv1: 3->32, 256x256, s1, p1, ReLU ----------------
// grid (8,16,64) block (16,16). Thread: 2 pixels x 32 oc (16 oc-pairs, f32x2).
__global__ void conv1_kernel(const float* __restrict__ imgA,
                             const float* __restrict__ imgB,
                             const float* __restrict__ w1,
                             const float* __restrict__ b1) {
    __shared__ __align__(16) float ws[27 * 32 + 4];   // [k][oc], padded even
    __shared__ __align__(16) float bs[32];
    int t = threadIdx.y * 16 + threadIdx.x;
    for (int i = t; i < 864; i += 256) {
        int k = i >> 5, oc = i & 31;
        ws[i] = w1[oc * 27 + k];
    }
    if (t < 32) bs[t] = b1[t];
    __syncthreads();

    int img = blockIdx.z >> 5;
    int b   = blockIdx.z & 31;
    const float* src = (img == 0 ? imgA : imgB) + (size_t)b * 3 * 256 * 256;
    float* dst = g_c1 + (size_t)img * C1_PER + (size_t)b * 32 * 256 * 256;

    int y  = blockIdx.y * 16 + threadIdx.y;
    int x0 = blockIdx.x * 32 + threadIdx.x;
    int x1 = x0 + 16;

    float in0[27], in1[27];
    #pragma unroll
    for (int c = 0; c < 3; c++)
        #pragma unroll
        for (int r = 0; r < 3; r++)
            #pragma unroll
            for (int s = 0; s < 3; s++) {
                int iy = y + r - 1;
                int ixa = x0 + s - 1;
                int ixb = x1 + s - 1;
                bool vy = (iy >= 0) && (iy < 256);
                const float* p = src + ((size_t)c * 256 + iy) * 256;
                int k = c * 9 + r * 3 + s;
                in0[k] = (vy && ixa >= 0 && ixa < 256) ? p[ixa] : 0.f;
                in1[k] = (vy && ixb < 256)             ? p[ixb] : 0.f;
            }

    ull acc0[16], acc1[16];
    #pragma unroll
    for (int jp = 0; jp < 16; jp++) {
        ull bb = *(const ull*)&bs[jp * 2];
        acc0[jp] = bb; acc1[jp] = bb;
    }

    #pragma unroll
    for (int k = 0; k < 27; k++) {
        ull v0 = packff(in0[k], in0[k]);
        ull v1 = packff(in1[k], in1[k]);
        #pragma unroll
        for (int jp = 0; jp < 16; jp++) {
            ull W = *(const ull*)&ws[k * 32 + jp * 2];
            acc0[jp] = fma2(v0, W, acc0[jp]);
            acc1[jp] = fma2(v1, W, acc1[jp]);
        }
    }

    #pragma unroll
    for (int jp = 0; jp < 16; jp++) {
        float2 f0 = unpack2(acc0[jp]);
        float2 f1 = unpack2(acc1[jp]);
        float* qa = dst + ((size_t)(jp * 2)     * 256 + y) * 256;
        float* qb = dst + ((size_t)(jp * 2 + 1) * 256 + y) * 256;
        qa[x0] = fmaxf(f0.x, 0.f);
        qb[x0] = fmaxf(f0.y, 0.f);
        qa[x1] = fmaxf(f1.x, 0.f);
        qb[x1] = fmaxf(f1.y, 0.f);
    }
}

// ---------------- conv2: 32->64, out 128x128, s2, p1, ReLU ----------------
// grid (8,8,64) block 256. Thread: 4 pixels x 16 oc (8 oc-pairs f32x2).
__global__ void __launch_bounds__(256, 2)
conv2_kernel(const float* __restrict__ w2, const float* __restrict__ b2) {
    __shared__ __align__(16) float wsm[9 * 64];       // [k][oc] -- declared FIRST, 16B aligned
    __shared__ __align__(16) float tile[33 * 33 + 3]; // padded to multiple of 4
    int t = threadIdx.x;
    int img = blockIdx.z >> 5, b = blockIdx.z & 31;
    const float* src = g_c1 + (size_t)img * C1_PER + (size_t)b * 32 * 256 * 256;
    float* dst = g_c2 + (size_t)img * C2_PER + (size_t)b * 64 * 128 * 128;

    int oy0 = blockIdx.y * 16, ox0 = blockIdx.x * 16;
    int iy0 = oy0 * 2 - 1, ix0 = ox0 * 2 - 1;

    int ocs = t >> 6;                 // warp-uniform oc group
    int ps  = t & 63;
    int py  = ps >> 3, px = ps & 7;
    int oc0 = ocs * 16;

    ull acc[4][8];
    #pragma unroll
    for (int jp = 0; jp < 8; jp++) {
        ull bb = packff(b2[oc0 + jp * 2], b2[oc0 + jp * 2 + 1]);
        #pragma unroll
        for (int a = 0; a < 4; a++) acc[a][jp] = bb;
    }

    for (int ic = 0; ic < 32; ic++) {
        __syncthreads();
        for (int i = t; i < 33 * 33; i += 256) {
            int ry = i / 33, rx = i % 33;
            int iy = iy0 + ry, ix = ix0 + rx;
            tile[i] = (iy >= 0 && iy < 256 && ix >= 0 && ix < 256)
                      ? src[((size_t)ic * 256 + iy) * 256 + ix] : 0.f;
        }
        for (int i = t; i < 576; i += 256) {
            int k = i >> 6, oc = i & 63;
            wsm[i] = w2[(size_t)oc * 288 + (size_t)ic * 9 + k];
        }
        __syncthreads();

        #pragma unroll
        for (int r = 0; r < 3; r++)
            #pragma unroll
            for (int s = 0; s < 3; s++) {
                int k = r * 3 + s;
                ull W[8];
                #pragma unroll
                for (int jp = 0; jp < 8; jp++)
                    W[jp] = *(const ull*)&wsm[k * 64 + oc0 + jp * 2];
                #pragma unroll
                for (int aa = 0; aa < 2; aa++)
                    #pragma unroll
                    for (int bb2_ = 0; bb2_ < 2; bb2_++) {
                        float v = tile[((py + 8 * aa) * 2 + r) * 33 + (px + 8 * bb2_) * 2 + s];
                        ull vv = packff(v, v);
                        int a = aa * 2 + bb2_;
                        #pragma unroll
                        for (int jp = 0; jp < 8; jp++)
                            acc[a][jp] = fma2(vv, W[jp], acc[a][jp]);
                    }
            }
    }

    #pragma unroll
    for (int aa = 0; aa < 2; aa++)
        #pragma unroll
        for (int bb2_ = 0; bb2_ < 2; bb2_++) {
            int oy = oy0 + py + 8 * aa;
            int ox = ox0 + px + 8 * bb2_;
            int a = aa * 2 + bb2_;
            #pragma unroll
            for (int jp = 0; jp < 8; jp++) {
                float2 f = unpack2(acc[a][jp]);
                dst[((size_t)(oc0 + jp * 2)     * 128 + oy) * 128 + ox] = fmaxf(f.x, 0.f);
                dst[((size_t)(oc0 + jp * 2 + 1) * 128 + oy) * 128 + ox] = fmaxf(f.y, 0.f);
            }
        }
}

// ---------------- conv3: 64->128, out 64x64, s2, p1, ReLU -> d_out ----------------
// grid (4,8,64) block 256. Thread: 4 pixels x 16 oc (8 oc-pairs f32x2).
__global__ void __launch_bounds__(256, 2)
conv3_kernel(const float* __restrict__ w3, const float* __restrict__ b3,
             float* __restrict__ out_all) {
    __shared__ __align__(16) float wsm[9 * 128];      // [k][oc] -- declared FIRST, 16B aligned
    __shared__ __align__(16) float tile[17 * 33 + 3]; // padded to multiple of 4
    int t = threadIdx.x;
    int img = blockIdx.z >> 5, b = blockIdx.z & 31;
    const float* src = g_c2 + (size_t)img * C2_PER + (size_t)b * 64 * 128 * 128;
    float* dst = out_all + (img == 0 ? OFF_ZT : OFF_ZT1) + (size_t)b * 128 * 64 * 64;

    int oy0 = blockIdx.y * 8, ox0 = blockIdx.x * 16;
    int iy0 = oy0 * 2 - 1, ix0 = ox0 * 2 - 1;

    int ocs = t >> 5;                 // warp-uniform oc group
    int ps  = t & 31;
    int py  = ps >> 2, px = ps & 3;
    int oc0 = ocs * 16;

    ull acc[4][8];
    #pragma unroll
    for (int jp = 0; jp < 8; jp++) {
        ull bb = packff(b3[oc0 + jp * 2], b3[oc0 + jp * 2 + 1]);
        #pragma unroll
        for (int a = 0; a < 4; a++) acc[a][jp] = bb;
    }

    for (int ic = 0; ic < 64; ic++) {
        __syncthreads();
        for (int i = t; i < 17 * 33; i += 256) {
            int ry = i / 33, rx = i % 33;
            int iy = iy0 + ry, ix = ix0 + rx;
            tile[i] = (iy >= 0 && iy < 128 && ix >= 0 && ix < 128)
                      ? src[((size_t)ic * 128 + iy) * 128 + ix] : 0.f;
        }
        for (int i = t; i < 1152; i += 256) {
            int k = i >> 7, oc = i & 127;
            wsm[i] = w3[(size_t)oc * 576 + (size_t)ic * 9 + k];
        }
        __syncthreads();

        #pragma unroll
        for (int r = 0; r < 3; r++)
            #pragma unroll
            for (int s = 0; s < 3; s++) {
                int k = r * 3 + s;
                ull W[8];
                #pragma unroll
                for (int jp = 0; jp < 8; jp++)
                    W[jp] = *(const ull*)&wsm[k * 128 + oc0 + jp * 2];
                #pragma unroll
                for (int bb3 = 0; bb3 < 4; bb3++) {
                    float v = tile[(py * 2 + r) * 33 + (px + 4 * bb3) * 2 + s];
                    ull vv = packff(v, v);
                    #pragma unroll
                    for (int jp = 0; jp < 8; jp++)
                        acc[bb3][jp] = fma2(vv, W[jp], acc[bb3][jp]);
                }
            }
    }

    int oy = oy0 + py;
    #pragma unroll
    for (int bb3 = 0; bb3 < 4; bb3++) {
        int ox = ox0 + px + 4 * bb3;
        #pragma unroll
        for (int jp = 0; jp < 8; jp++) {
            float2 f = unpack2(acc[bb3][jp]);
            dst[((size_t)(oc0 + jp * 2)     * 64 + oy) * 64 + ox] = fmaxf(f.x, 0.f);
            dst[((size_t)(oc0 + jp * 2 + 1) * 64 + oy) * 64 + ox] = fmaxf(f.y, 0.f);
        }
    }
}

// ---------------- corr: register-tiled, 4 px x 13 dj per thread, di split over 4 ----------------
// grid (4,4,32) block 256. smem acc [169][256] persists over channel chunks.
__global__ void __launch_bounds__(256, 1)
corr_kernel(float* __restrict__ out_all) {
    extern __shared__ __align__(16) float sm[];
    float* accs = sm;                    // [169][256]
    float* ztt  = sm + 169 * 256;        // [8][256]  ([c][pix])
    float* z1t  = ztt + 2048;            // [8][28][28]

    int t = threadIdx.x;
    int b = blockIdx.z;
    int gy0 = blockIdx.y * 16, gx0 = blockIdx.x * 16;
    const float* zt  = out_all + OFF_ZT  + (size_t)b * 128 * 4096;
    const float* zt1 = out_all + OFF_ZT1 + (size_t)b * 128 * 4096;

    for (int i = t; i < 169 * 256; i += 256) accs[i] = 0.f;

    int g   = t & 63;         // pixel group (warp-contiguous)
    int tdi = t >> 6;         // di sub-group (warp-uniform)
    int ty  = g >> 2;
    int gx4 = (g & 3) << 2;
    int ndis = (tdi == 0) ? 4 : 3;
    int dis[4] = {tdi, tdi + 4, tdi + 8, 12};

    for (int cc = 0; cc < 16; cc++) {
        __syncthreads();
        #pragma unroll
        for (int k = 0; k < 8; k++)
            ztt[k * 256 + t] = zt[((size_t)(cc * 8 + k)) * 4096 +
                                  (gy0 + (t >> 4)) * 64 + gx0 + (t & 15)];
        for (int i = t; i < 8 * 784; i += 256) {
            int c = i / 784, rem = i - c * 784;
            int yy = rem / 28, xx = rem - yy * 28;
            int gy = gy0 - 6 + yy, gx = gx0 - 6 + xx;
            z1t[i] = (gy >= 0 && gy < 64 && gx >= 0 && gx < 64)
                     ? zt1[((size_t)(cc * 8 + c)) * 4096 + gy * 64 + gx] : 0.f;
        }
        __syncthreads();

        for (int dd = 0; dd < ndis; dd++) {
            int di = dis[dd];
            float p[13][4];
            #pragma unroll
            for (int dj = 0; dj < 13; dj++)
                #pragma unroll
                for (int q = 0; q < 4; q++) p[dj][q] = 0.f;

            #pragma unroll
            for (int c = 0; c < 8; c++) {
                float4 z4 = *(const float4*)&ztt[c * 256 + g * 4];
                const float* rb = &z1t[c * 784 + (ty + di) * 28 + gx4];
                float4 r0 = *(const float4*)(rb);
                float4 r1 = *(const float4*)(rb + 4);
                float4 r2 = *(const float4*)(rb + 8);
                float4 r3 = *(const float4*)(rb + 12);
                float rv[16] = {r0.x, r0.y, r0.z, r0.w, r1.x, r1.y, r1.z, r1.w,
                                r2.x, r2.y, r2.z, r2.w, r3.x, r3.y, r3.z, r3.w};
                #pragma unroll
                for (int dj = 0; dj < 13; dj++) {
                    p[dj][0] += z4.x * rv[dj];
                    p[dj][1] += z4.y * rv[dj + 1];
                    p[dj][2] += z4.z * rv[dj + 2];
                    p[dj][3] += z4.w * rv[dj + 3];
                }
            }
            #pragma unroll
            for (int dj = 0; dj < 13; dj++) {
                float4* ap = (float4*)&accs[(di * 13 + dj) * 256 + g * 4];
                float4 av = *ap;
                av.x += p[dj][0]; av.y += p[dj][1];
                av.z += p[dj][2]; av.w += p[dj][3];
                *ap = av;
            }
        }
    }
    __syncthreads();

    const float inv = 0.0883883476483184f;   // 1/sqrt(128)
    float* co = out_all + OFF_CORR + (size_t)b * 169 * 4096;
    int gy = gy0 + (t >> 4), gx = gx0 + (t & 15);
    for (int o = 0; o < 169; o++)
        co[(size_t)o * 4096 + gy * 64 + gx] = accs[o * 256 + t] * inv;
}

// ---------------- h_t: spatial mean of corr ----------------
__global__ void ht_kernel(float* __restrict__ out_all) {
    int o = blockIdx.x, b = blockIdx.y;
    const float4* co = (const float4*)(out_all + OFF_CORR + ((size_t)b * 169 + o) * 4096);
    float s = 0.f;
    for (int i = threadIdx.x; i < 1024; i += 256) {
        float4 v = co[i];
        s += (v.x + v.y) + (v.z + v.w);
    }
    __shared__ float red[8];
    #pragma unroll
    for (int off = 16; off; off >>= 1) s += __shfl_down_sync(0xffffffffu, s, off);
    if ((threadIdx.x & 31) == 0) red[threadIdx.x >> 5] = s;
    __syncthreads();
    if (threadIdx.x < 8) {
        s = red[threadIdx.x];
        #pragma unroll
        for (int off = 4; off; off >>= 1) s += __shfl_down_sync(0xffu, s, off);
        if (threadIdx.x == 0) out_all[OFF_HT + b * 169 + o] = s * (1.f / 4096.f);
    }
}

// ---------------- head ----------------
__global__ void head_kernel(float* __restrict__ out_all,
                            const float* __restrict__ wh,
                            const float* __restrict__ bh) {
    int t = threadIdx.x;
    if (t >= 64) return;
    int b = t >> 1, j = t & 1;
    const float* h = out_all + OFF_HT + b * 169;
    float s = bh[j];
    for (int o = 0; o < 169; o++) s += h[o] * wh[j * 169 + o];
    out_all[OFF_PRED + b * 2 + j] = s;
}

// ---------------- launch ----------------
extern "C" void kernel_launch(void* const* d_in, const int* in_sizes, int n_in,
                              void* d_out, int out_size) {
    const float* img_t  = (const float*)d_in[0];
    const float* img_t1 = (const float*)d_in[1];
    const float* w1 = (const float*)d_in[2];
    const float* b1 = (const float*)d_in[3];
    const float* w2 = (const float*)d_in[4];
    const float* b2 = (const float*)d_in[5];
    const float* w3 = (const float*)d_in[6];
    const float* b3 = (const float*)d_in[7];
    const float* wh = (const float*)d_in[8];
    const float* bh = (const float*)d_in[9];
    float* out = (float*)d_out;

    conv1_kernel<<<dim3(8, 16, 64), dim3(16, 16)>>>(img_t, img_t1, w1, b1);
    conv2_kernel<<<dim3(8, 8, 64), 256>>>(w2, b2);
    conv3_kernel<<<dim3(4, 8, 64), 256>>>(w3, b3, out);

    int corr_smem = (169 * 256 + 2048 + 8 * 784) * 4;   // 206,336 B
    cudaFuncSetAttribute(corr_kernel, cudaFuncAttributeMaxDynamicSharedMemorySize, corr_smem);
    corr_kernel<<<dim3(4, 4, 32), 256, corr_smem>>>(out);

    ht_kernel<<<dim3(169, 32), 256>>>(out);
    head_kernel<<<1, 64>>>(out, wh, bh);
}

// round 13
// speedup vs baseline: 1.5956x; 1.2517x over previous
#include <cuda_runtime.h>

// ---------------- sizes / offsets ----------------
static const size_t C1_PER = 32ull * 32 * 256 * 256;
static const size_t C2_PER = 32ull * 64 * 128 * 128;

#define OFF_PRED 0
#define OFF_ZT   64
#define OFF_ZT1  (64 + 32*128*64*64)
#define OFF_CORR (OFF_ZT1 + 32*128*64*64)
#define OFF_HT   (OFF_CORR + 32*169*64*64)

// ---------------- scratch ----------------
__device__ float g_c1[2ull * 32 * 32 * 256 * 256];
__device__ float g_c2[2ull * 32 * 64 * 128 * 128];

// ---------------- f32x2 helpers ----------------
typedef unsigned long long ull;
__device__ __forceinline__ ull fma2(ull a, ull b, ull c) {
    ull d;
    asm("fma.rn.f32x2 %0, %1, %2, %3;" : "=l"(d) : "l"(a), "l"(b), "l"(c));
    return d;
}
__device__ __forceinline__ ull packff(float lo, float hi) {
    ull d;
    asm("mov.b64 %0, {%1, %2};" : "=l"(d) : "f"(lo), "f"(hi));
    return d;
}
__device__ __forceinline__ float2 unpack2(ull v) {
    float2 f;
    asm("mov.b64 {%0, %1}, %2;" : "=f"(f.x), "=f"(f.y) : "l"(v));
    return f;
}

// ---------------- conv1: 3->32, 256x256, s1, p1, ReLU ----------------
__global__ void conv1_kernel(const float* __restrict__ imgA,
                             const float* __restrict__ imgB,
                             const float* __restrict__ w1,
                             const float* __restrict__ b1) {
    __shared__ __align__(16) float ws[27 * 32 + 4];
    __shared__ __align__(16) float bs[32];
    int t = threadIdx.y * 16 + threadIdx.x;
    for (int i = t; i < 864; i += 256) {
        int k = i >> 5, oc = i & 31;
        ws[i] = w1[oc * 27 + k];
    }
    if (t < 32) bs[t] = b1[t];
    __syncthreads();

    int img = blockIdx.z >> 5;
    int b   = blockIdx.z & 31;
    const float* src = (img == 0 ? imgA : imgB) + (size_t)b * 3 * 256 * 256;
    float* dst = g_c1 + (size_t)img * C1_PER + (size_t)b * 32 * 256 * 256;

    int y  = blockIdx.y * 16 + threadIdx.y;
    int x0 = blockIdx.x * 32 + threadIdx.x;
    int x1 = x0 + 16;

    float in0[27], in1[27];
    #pragma unroll
    for (int c = 0; c < 3; c++)
        #pragma unroll
        for (int r = 0; r < 3; r++)
            #pragma unroll
            for (int s = 0; s < 3; s++) {
                int iy = y + r - 1;
                int ixa = x0 + s - 1;
                int ixb = x1 + s - 1;
                bool vy = (iy >= 0) && (iy < 256);
                const float* p = src + ((size_t)c * 256 + iy) * 256;
                int k = c * 9 + r * 3 + s;
                in0[k] = (vy && ixa >= 0 && ixa < 256) ? p[ixa] : 0.f;
                in1[k] = (vy && ixb < 256)             ? p[ixb] : 0.f;
            }

    ull acc0[16], acc1[16];
    #pragma unroll
    for (int jp = 0; jp < 16; jp++) {
        ull bb = *(const ull*)&bs[jp * 2];
        acc0[jp] = bb; acc1[jp] = bb;
    }

    #pragma unroll
    for (int k = 0; k < 27; k++) {
        ull v0 = packff(in0[k], in0[k]);
        ull v1 = packff(in1[k], in1[k]);
        #pragma unroll
        for (int jp = 0; jp < 16; jp++) {
            ull W = *(const ull*)&ws[k * 32 + jp * 2];
            acc0[jp] = fma2(v0, W, acc0[jp]);
            acc1[jp] = fma2(v1, W, acc1[jp]);
        }
    }

    #pragma unroll
    for (int jp = 0; jp < 16; jp++) {
        float2 f0 = unpack2(acc0[jp]);
        float2 f1 = unpack2(acc1[jp]);
        float* qa = dst + ((size_t)(jp * 2)     * 256 + y) * 256;
        float* qb = dst + ((size_t)(jp * 2 + 1) * 256 + y) * 256;
        qa[x0] = fmaxf(f0.x, 0.f);
        qb[x0] = fmaxf(f0.y, 0.f);
        qa[x1] = fmaxf(f1.x, 0.f);
        qb[x1] = fmaxf(f1.y, 0.f);
    }
}

// ---------------- conv2: 32->64, out 128x128, s2, p1, ReLU, double-buffered ----------------
__device__ __forceinline__ void c2_ldg(const float* __restrict__ src,
                                       const float* __restrict__ w2,
                                       int ic, int iy0, int ix0, int t,
                                       float tr[5], float wr[3]) {
    #pragma unroll
    for (int u = 0; u < 5; u++) {
        int i = t + u * 256;
        if (i < 1089) {
            int ry = i / 33, rx = i % 33;
            int iy = iy0 + ry, ix = ix0 + rx;
            tr[u] = (iy >= 0 && iy < 256 && ix >= 0 && ix < 256)
                    ? src[((size_t)ic * 256 + iy) * 256 + ix] : 0.f;
        }
    }
    #pragma unroll
    for (int u = 0; u < 3; u++) {
        int i = t + u * 256;
        if (i < 576) {
            int k = i >> 6, oc = i & 63;
            wr[u] = w2[(size_t)oc * 288 + (size_t)ic * 9 + k];
        }
    }
}
__device__ __forceinline__ void c2_sts(float* tb, float* wb, int t,
                                       const float tr[5], const float wr[3]) {
    #pragma unroll
    for (int u = 0; u < 5; u++) { int i = t + u * 256; if (i < 1089) tb[i] = tr[u]; }
    #pragma unroll
    for (int u = 0; u < 3; u++) { int i = t + u * 256; if (i < 576)  wb[i] = wr[u]; }
}

__global__ void __launch_bounds__(256, 2)
conv2_kernel(const float* __restrict__ w2, const float* __restrict__ b2) {
    __shared__ __align__(16) float wsm[2][576];
    __shared__ __align__(16) float tile[2][1089 + 3];
    int t = threadIdx.x;
    int img = blockIdx.z >> 5, b = blockIdx.z & 31;
    const float* src = g_c1 + (size_t)img * C1_PER + (size_t)b * 32 * 256 * 256;
    float* dst = g_c2 + (size_t)img * C2_PER + (size_t)b * 64 * 128 * 128;

    int oy0 = blockIdx.y * 16, ox0 = blockIdx.x * 16;
    int iy0 = oy0 * 2 - 1, ix0 = ox0 * 2 - 1;

    int ocs = t >> 6;
    int ps  = t & 63;
    int py  = ps >> 3, px = ps & 7;
    int oc0 = ocs * 16;

    ull acc[4][8];
    #pragma unroll
    for (int jp = 0; jp < 8; jp++) {
        ull bb = packff(b2[oc0 + jp * 2], b2[oc0 + jp * 2 + 1]);
        #pragma unroll
        for (int a = 0; a < 4; a++) acc[a][jp] = bb;
    }

    {
        float tr[5], wr[3];
        c2_ldg(src, w2, 0, iy0, ix0, t, tr, wr);
        c2_sts(tile[0], wsm[0], t, tr, wr);
    }
    __syncthreads();

    for (int ic = 0; ic < 32; ic++) {
        int cur = ic & 1;
        float tr[5], wr[3];
        if (ic < 31) c2_ldg(src, w2, ic + 1, iy0, ix0, t, tr, wr);

        const float* tl = tile[cur];
        const float* wl = wsm[cur];
        #pragma unroll
        for (int r = 0; r < 3; r++)
            #pragma unroll
            for (int s = 0; s < 3; s++) {
                int k = r * 3 + s;
                ull W[8];
                #pragma unroll
                for (int jp = 0; jp < 8; jp++)
                    W[jp] = *(const ull*)&wl[k * 64 + oc0 + jp * 2];
                #pragma unroll
                for (int aa = 0; aa < 2; aa++)
                    #pragma unroll
                    for (int bb2_ = 0; bb2_ < 2; bb2_++) {
                        float v = tl[((py + 8 * aa) * 2 + r) * 33 + (px + 8 * bb2_) * 2 + s];
                        ull vv = packff(v, v);
                        int a = aa * 2 + bb2_;
                        #pragma unroll
                        for (int jp = 0; jp < 8; jp++)
                            acc[a][jp] = fma2(vv, W[jp], acc[a][jp]);
                    }
            }

        if (ic < 31) c2_sts(tile[cur ^ 1], wsm[cur ^ 1], t, tr, wr);
        __syncthreads();
    }

    #pragma unroll
    for (int aa = 0; aa < 2; aa++)
        #pragma unroll
        for (int bb2_ = 0; bb2_ < 2; bb2_++) {
            int oy = oy0 + py + 8 * aa;
            int ox = ox0 + px + 8 * bb2_;
            int a = aa * 2 + bb2_;
            #pragma unroll
            for (int jp = 0; jp < 8; jp++) {
                float2 f = unpack2(acc[a][jp]);
                dst[((size_t)(oc0 + jp * 2)     * 128 + oy) * 128 + ox] = fmaxf(f.x, 0.f);
                dst[((size_t)(oc0 + jp * 2 + 1) * 128 + oy) * 128 + ox] = fmaxf(f.y, 0.f);
            }
        }
}

// ---------------- conv3: 64->128, out 64x64, s2, p1, ReLU, double-buffered ----------------
__device__ __forceinline__ void c3_ldg(const float* __restrict__ src,
                                       const float* __restrict__ w3,
                                       int ic, int iy0, int ix0, int t,
                                       float tr[3], float wr[5]) {
    #pragma unroll
    for (int u = 0; u < 3; u++) {
        int i = t + u * 256;
        if (i < 561) {
            int ry = i / 33, rx = i % 33;
            int iy = iy0 + ry, ix = ix0 + rx;
            tr[u] = (iy >= 0 && iy < 128 && ix >= 0 && ix < 128)
                    ? src[((size_t)ic * 128 + iy) * 128 + ix] : 0.f;
        }
    }
    #pragma unroll
    for (int u = 0; u < 5; u++) {
        int i = t + u * 256;
        if (i < 1152) {
            int k = i >> 7, oc = i & 127;
            wr[u] = w3[(size_t)oc * 576 + (size_t)ic * 9 + k];
        }
    }
}
__device__ __forceinline__ void c3_sts(float* tb, float* wb, int t,
                                       const float tr[3], const float wr[5]) {
    #pragma unroll
    for (int u = 0; u < 3; u++) { int i = t + u * 256; if (i < 561)  tb[i] = tr[u]; }
    #pragma unroll
    for (int u = 0; u < 5; u++) { int i = t + u * 256; if (i < 1152) wb[i] = wr[u]; }
}

__global__ void __launch_bounds__(256, 2)
conv3_kernel(const float* __restrict__ w3, const float* __restrict__ b3,
             float* __restrict__ out_all) {
    __shared__ __align__(16) float wsm[2][1152];
    __shared__ __align__(16) float tile[2][561 + 3];
    int t = threadIdx.x;
    int img = blockIdx.z >> 5, b = blockIdx.z & 31;
    const float* src = g_c2 + (size_t)img * C2_PER + (size_t)b * 64 * 128 * 128;
    float* dst = out_all + (img == 0 ? OFF_ZT : OFF_ZT1) + (size_t)b * 128 * 64 * 64;

    int oy0 = blockIdx.y * 8, ox0 = blockIdx.x * 16;
    int iy0 = oy0 * 2 - 1, ix0 = ox0 * 2 - 1;

    int ocs = t >> 5;
    int ps  = t & 31;
    int py  = ps >> 2, px = ps & 3;
    int oc0 = ocs * 16;

    ull acc[4][8];
    #pragma unroll
    for (int jp = 0; jp < 8; jp++) {
        ull bb = packff(b3[oc0 + jp * 2], b3[oc0 + jp * 2 + 1]);
        #pragma unroll
        for (int a = 0; a < 4; a++) acc[a][jp] = bb;
    }

    {
        float tr[3], wr[5];
        c3_ldg(src, w3, 0, iy0, ix0, t, tr, wr);
        c3_sts(tile[0], wsm[0], t, tr, wr);
    }
    __syncthreads();

    for (int ic = 0; ic < 64; ic++) {
        int cur = ic & 1;
        float tr[3], wr[5];
        if (ic < 63) c3_ldg(src, w3, ic + 1, iy0, ix0, t, tr, wr);

        const float* tl = tile[cur];
        const float* wl = wsm[cur];
        #pragma unroll
        for (int r = 0; r < 3; r++)
            #pragma unroll
            for (int s = 0; s < 3; s++) {
                int k = r * 3 + s;
                ull W[8];
                #pragma unroll
                for (int jp = 0; jp < 8; jp++)
                    W[jp] = *(const ull*)&wl[k * 128 + oc0 + jp * 2];
                #pragma unroll
                for (int bb3 = 0; bb3 < 4; bb3++) {
                    float v = tl[(py * 2 + r) * 33 + (px + 4 * bb3) * 2 + s];
                    ull vv = packff(v, v);
                    #pragma unroll
                    for (int jp = 0; jp < 8; jp++)
                        acc[bb3][jp] = fma2(vv, W[jp], acc[bb3][jp]);
                }
            }

        if (ic < 63) c3_sts(tile[cur ^ 1], wsm[cur ^ 1], t, tr, wr);
        __syncthreads();
    }

    int oy = oy0 + py;
    #pragma unroll
    for (int bb3 = 0; bb3 < 4; bb3++) {
        int ox = ox0 + px + 4 * bb3;
        #pragma unroll
        for (int jp = 0; jp < 8; jp++) {
            float2 f = unpack2(acc[bb3][jp]);
            dst[((size_t)(oc0 + jp * 2)     * 64 + oy) * 64 + ox] = fmaxf(f.x, 0.f);
            dst[((size_t)(oc0 + jp * 2 + 1) * 64 + oy) * 64 + ox] = fmaxf(f.y, 0.f);
        }
    }
}

// ---------------- corr: di-split halves, 2 CTAs/SM target ----------------
// grid (4,4,64): z = b*2 + half. half0: di 0..6 (7), half1: di 7..12 (6).
// smem: acc [ndi*13][256] + z1t [8][nrows][28], nrows = ndi+15.
__global__ void __launch_bounds__(256, 2)
corr_kernel(float* __restrict__ out_all) {
    extern __shared__ __align__(16) float sm[];
    int t = threadIdx.x;
    int half = blockIdx.z & 1;
    int b    = blockIdx.z >> 1;
    int di_lo = half ? 7 : 0;
    int ndi   = half ? 6 : 7;
    int nrows = ndi + 15;            // 22 or 21
    int rowsz = nrows * 28;

    float* accs = sm;                // [ndi*13][256]
    float* z1t  = sm + ndi * 13 * 256;

    int gy0 = blockIdx.y * 16, gx0 = blockIdx.x * 16;
    const float* zt  = out_all + OFF_ZT  + (size_t)b * 128 * 4096;
    const float* zt1 = out_all + OFF_ZT1 + (size_t)b * 128 * 4096;

    for (int i = t; i < ndi * 13 * 256; i += 256) accs[i] = 0.f;

    int g   = t & 63;                // pixel group: 4 consecutive px
    int tdi = t >> 6;                // di sub-group (warp-uniform)
    int ty  = g >> 2;
    int gx4 = (g & 3) << 2;
    int d0 = tdi, d1 = tdi + 4;      // local di indices
    int nd = (d1 < ndi) ? 2 : ((d0 < ndi) ? 1 : 0);

    for (int cc = 0; cc < 16; cc++) {
        __syncthreads();
        // stage z1 window rows [di_lo .. di_lo+nrows-1] for 8 channels
        for (int c = 0; c < 8; c++) {
            const float* zsrc = zt1 + ((size_t)(cc * 8 + c)) * 4096;
            float* zd = z1t + c * rowsz;
            #pragma unroll
            for (int u = 0; u < 3; u++) {
                int i = t + u * 256;
                if (i < rowsz) {
                    int yy = i / 28, xx = i - yy * 28;
                    int gy = gy0 - 6 + di_lo + yy, gx = gx0 - 6 + xx;
                    zd[i] = (gy >= 0 && gy < 64 && gx >= 0 && gx < 64)
                            ? zsrc[gy * 64 + gx] : 0.f;
                }
            }
        }
        __syncthreads();

        for (int dd = 0; dd < nd; dd++) {
            int dl = (dd == 0) ? d0 : d1;   // local di
            float p[13][4];
            #pragma unroll
            for (int dj = 0; dj < 13; dj++)
                #pragma unroll
                for (int q = 0; q < 4; q++) p[dj][q] = 0.f;

            #pragma unroll
            for (int c = 0; c < 8; c++) {
                float4 z4 = *(const float4*)&zt[((size_t)(cc * 8 + c)) * 4096 +
                                                (gy0 + ty) * 64 + gx0 + gx4];
                const float* rb = &z1t[c * rowsz + (ty + dl) * 28 + gx4];
                float4 r0 = *(const float4*)(rb);
                float4 r1 = *(const float4*)(rb + 4);
                float4 r2 = *(const float4*)(rb + 8);
                float4 r3 = *(const float4*)(rb + 12);
                float rv[16] = {r0.x, r0.y, r0.z, r0.w, r1.x, r1.y, r1.z, r1.w,
                                r2.x, r2.y, r2.z, r2.w, r3.x, r3.y, r3.z, r3.w};
                #pragma unroll
                for (int dj = 0; dj < 13; dj++) {
                    p[dj][0] += z4.x * rv[dj];
                    p[dj][1] += z4.y * rv[dj + 1];
                    p[dj][2] += z4.z * rv[dj + 2];
                    p[dj][3] += z4.w * rv[dj + 3];
                }
            }
            #pragma unroll
            for (int dj = 0; dj < 13; dj++) {
                float4* ap = (float4*)&accs[(dl * 13 + dj) * 256 + g * 4];
                float4 av = *ap;
                av.x += p[dj][0]; av.y += p[dj][1];
                av.z += p[dj][2]; av.w += p[dj][3];
                *ap = av;
            }
        }
    }
    __syncthreads();

    const float inv = 0.0883883476483184f;   // 1/sqrt(128)
    float* co = out_all + OFF_CORR + (size_t)b * 169 * 4096;
    int gy = gy0 + (t >> 4), gx = gx0 + (t & 15);
    for (int o = 0; o < ndi * 13; o++)
        co[(size_t)(di_lo * 13 + o) * 4096 + gy * 64 + gx] = accs[o * 256 + t] * inv;
}

// ---------------- h_t: spatial mean of corr ----------------
__global__ void ht_kernel(float* __restrict__ out_all) {
    int o = blockIdx.x, b = blockIdx.y;
    const float4* co = (const float4*)(out_all + OFF_CORR + ((size_t)b * 169 + o) * 4096);
    float s = 0.f;
    for (int i = threadIdx.x; i < 1024; i += 256) {
        float4 v = co[i];
        s += (v.x + v.y) + (v.z + v.w);
    }
    __shared__ float red[8];
    #pragma unroll
    for (int off = 16; off; off >>= 1) s += __shfl_down_sync(0xffffffffu, s, off);
    if ((threadIdx.x & 31) == 0) red[threadIdx.x >> 5] = s;
    __syncthreads();
    if (threadIdx.x < 8) {
        s = red[threadIdx.x];
        #pragma unroll
        for (int off = 4; off; off >>= 1) s += __shfl_down_sync(0xffu, s, off);
        if (threadIdx.x == 0) out_all[OFF_HT + b * 169 + o] = s * (1.f / 4096.f);
    }
}

// ---------------- head ----------------
__global__ void head_kernel(float* __restrict__ out_all,
                            const float* __restrict__ wh,
                            const float* __restrict__ bh) {
    int t = threadIdx.x;
    if (t >= 64) return;
    int b = t >> 1, j = t & 1;
    const float* h = out_all + OFF_HT + b * 169;
    float s = bh[j];
    for (int o = 0; o < 169; o++) s += h[o] * wh[j * 169 + o];
    out_all[OFF_PRED + b * 2 + j] = s;
}

// ---------------- launch ----------------
extern "C" void kernel_launch(void* const* d_in, const int* in_sizes, int n_in,
                              void* d_out, int out_size) {
    const float* img_t  = (const float*)d_in[0];
    const float* img_t1 = (const float*)d_in[1];
    const float* w1 = (const float*)d_in[2];
    const float* b1 = (const float*)d_in[3];
    const float* w2 = (const float*)d_in[4];
    const float* b2 = (const float*)d_in[5];
    const float* w3 = (const float*)d_in[6];
    const float* b3 = (const float*)d_in[7];
    const float* wh = (const float*)d_in[8];
    const float* bh = (const float*)d_in[9];
    float* out = (float*)d_out;

    conv1_kernel<<<dim3(8, 16, 64), dim3(16, 16)>>>(img_t, img_t1, w1, b1);
    conv2_kernel<<<dim3(8, 8, 64), 256>>>(w2, b2);
    conv3_kernel<<<dim3(4, 8, 64), 256>>>(w3, b3, out);

    // half0 (7 dis): acc 91*256 + z1t 8*22*28 = 23296 + 4928 floats = 112,896 B
    int corr_smem = (91 * 256 + 8 * 22 * 28) * 4;
    cudaFuncSetAttribute(corr_kernel, cudaFuncAttributeMaxDynamicSharedMemorySize, corr_smem);
    corr_kernel<<<dim3(4, 4, 64), 256, corr_smem>>>(out);

    ht_kernel<<<dim3(169, 32), 256>>>(out);
    head_kernel<<<1, 64>>>(out, wh, bh);
}

// round 16
// speedup vs baseline: 1.5984x; 1.0018x over previous
#include <cuda_runtime.h>

// ---------------- sizes / offsets ----------------
static const size_t C1_PER = 32ull * 32 * 256 * 256;
static const size_t C2_PER = 32ull * 64 * 128 * 128;

#define OFF_PRED 0
#define OFF_ZT   64
#define OFF_ZT1  (64 + 32*128*64*64)
#define OFF_CORR (OFF_ZT1 + 32*128*64*64)
#define OFF_HT   (OFF_CORR + 32*169*64*64)

// ---------------- scratch ----------------
__device__ float g_c1[2ull * 32 * 32 * 256 * 256];
__device__ float g_c2[2ull * 32 * 64 * 128 * 128];

// ---------------- f32x2 helpers ----------------
typedef unsigned long long ull;
__device__ __forceinline__ ull fma2(ull a, ull b, ull c) {
    ull d;
    asm("fma.rn.f32x2 %0, %1, %2, %3;" : "=l"(d) : "l"(a), "l"(b), "l"(c));
    return d;
}
__device__ __forceinline__ ull packff(float lo, float hi) {
    ull d;
    asm("mov.b64 %0, {%1, %2};" : "=l"(d) : "f"(lo), "f"(hi));
    return d;
}
__device__ __forceinline__ float2 unpack2(ull v) {
    float2 f;
    asm("mov.b64 {%0, %1}, %2;" : "=f"(f.x), "=f"(f.y) : "l"(v));
    return f;
}

// ---------------- conv1: 3->32, 256x256, s1, p1, ReLU ----------------
__global__ void conv1_kernel(const float* __restrict__ imgA,
                             const float* __restrict__ imgB,
                             const float* __restrict__ w1,
                             const float* __restrict__ b1) {
    __shared__ __align__(16) float ws[27 * 32 + 4];
    __shared__ __align__(16) float bs[32];
    int t = threadIdx.y * 16 + threadIdx.x;
    for (int i = t; i < 864; i += 256) {
        int k = i >> 5, oc = i & 31;
        ws[i] = w1[oc * 27 + k];
    }
    if (t < 32) bs[t] = b1[t];
    __syncthreads();

    int img = blockIdx.z >> 5;
    int b   = blockIdx.z & 31;
    const float* src = (img == 0 ? imgA : imgB) + (size_t)b * 3 * 256 * 256;
    float* dst = g_c1 + (size_t)img * C1_PER + (size_t)b * 32 * 256 * 256;

    int y  = blockIdx.y * 16 + threadIdx.y;
    int x0 = blockIdx.x * 32 + threadIdx.x;
    int x1 = x0 + 16;

    float in0[27], in1[27];
    #pragma unroll
    for (int c = 0; c < 3; c++)
        #pragma unroll
        for (int r = 0; r < 3; r++)
            #pragma unroll
            for (int s = 0; s < 3; s++) {
                int iy = y + r - 1;
                int ixa = x0 + s - 1;
                int ixb = x1 + s - 1;
                bool vy = (iy >= 0) && (iy < 256);
                const float* p = src + ((size_t)c * 256 + iy) * 256;
                int k = c * 9 + r * 3 + s;
                in0[k] = (vy && ixa >= 0 && ixa < 256) ? p[ixa] : 0.f;
                in1[k] = (vy && ixb < 256)             ? p[ixb] : 0.f;
            }

    ull acc0[16], acc1[16];
    #pragma unroll
    for (int jp = 0; jp < 16; jp++) {
        ull bb = *(const ull*)&bs[jp * 2];
        acc0[jp] = bb; acc1[jp] = bb;
    }

    #pragma unroll
    for (int k = 0; k < 27; k++) {
        ull v0 = packff(in0[k], in0[k]);
        ull v1 = packff(in1[k], in1[k]);
        #pragma unroll
        for (int jp = 0; jp < 16; jp++) {
            ull W = *(const ull*)&ws[k * 32 + jp * 2];
            acc0[jp] = fma2(v0, W, acc0[jp]);
            acc1[jp] = fma2(v1, W, acc1[jp]);
        }
    }

    #pragma unroll
    for (int jp = 0; jp < 16; jp++) {
        float2 f0 = unpack2(acc0[jp]);
        float2 f1 = unpack2(acc1[jp]);
        float* qa = dst + ((size_t)(jp * 2)     * 256 + y) * 256;
        float* qb = dst + ((size_t)(jp * 2 + 1) * 256 + y) * 256;
        qa[x0] = fmaxf(f0.x, 0.f);
        qb[x0] = fmaxf(f0.y, 0.f);
        qa[x1] = fmaxf(f1.x, 0.f);
        qb[x1] = fmaxf(f1.y, 0.f);
    }
}

// ---------------- conv2: 32->64, out 128x128, s2, p1, ReLU, 2-ic double-buffered ----------------
__device__ __forceinline__ void c2_ldg(const float* __restrict__ src,
                                       const float* __restrict__ w2,
                                       int ic, int iy0, int ix0, int t,
                                       float tr[5], float wr[3]) {
    #pragma unroll
    for (int u = 0; u < 5; u++) {
        int i = t + u * 256;
        if (i < 1089) {
            int ry = i / 33, rx = i % 33;
            int iy = iy0 + ry, ix = ix0 + rx;
            tr[u] = (iy >= 0 && iy < 256 && ix >= 0 && ix < 256)
                    ? src[((size_t)ic * 256 + iy) * 256 + ix] : 0.f;
        }
    }
    #pragma unroll
    for (int u = 0; u < 3; u++) {
        int i = t + u * 256;
        if (i < 576) {
            int k = i >> 6, oc = i & 63;
            wr[u] = w2[(size_t)oc * 288 + (size_t)ic * 9 + k];
        }
    }
}
__device__ __forceinline__ void c2_sts(float* tb, float* wb, int t,
                                       const float tr[5], const float wr[3]) {
    #pragma unroll
    for (int u = 0; u < 5; u++) { int i = t + u * 256; if (i < 1089) tb[i] = tr[u]; }
    #pragma unroll
    for (int u = 0; u < 3; u++) { int i = t + u * 256; if (i < 576)  wb[i] = wr[u]; }
}

__global__ void __launch_bounds__(256, 2)
conv2_kernel(const float* __restrict__ w2, const float* __restrict__ b2) {
    __shared__ __align__(16) float wsm[2][2][576];
    __shared__ __align__(16) float tile[2][2][1089 + 3];
    int t = threadIdx.x;
    int img = blockIdx.z >> 5, b = blockIdx.z & 31;
    const float* src = g_c1 + (size_t)img * C1_PER + (size_t)b * 32 * 256 * 256;
    float* dst = g_c2 + (size_t)img * C2_PER + (size_t)b * 64 * 128 * 128;

    int oy0 = blockIdx.y * 16, ox0 = blockIdx.x * 16;
    int iy0 = oy0 * 2 - 1, ix0 = ox0 * 2 - 1;

    int ocs = t >> 6;
    int ps  = t & 63;
    int py  = ps >> 3, px = ps & 7;
    int oc0 = ocs * 16;

    ull acc[4][8];
    #pragma unroll
    for (int jp = 0; jp < 8; jp++) {
        ull bb = packff(b2[oc0 + jp * 2], b2[oc0 + jp * 2 + 1]);
        #pragma unroll
        for (int a = 0; a < 4; a++) acc[a][jp] = bb;
    }

    {
        float tr[2][5], wr[2][3];
        c2_ldg(src, w2, 0, iy0, ix0, t, tr[0], wr[0]);
        c2_ldg(src, w2, 1, iy0, ix0, t, tr[1], wr[1]);
        c2_sts(tile[0][0], wsm[0][0], t, tr[0], wr[0]);
        c2_sts(tile[0][1], wsm[0][1], t, tr[1], wr[1]);
    }
    __syncthreads();

    for (int p = 0; p < 16; p++) {          // 16 stages x 2 ic
        int cur = p & 1;
        float tr[2][5], wr[2][3];
        if (p < 15) {
            c2_ldg(src, w2, 2 * p + 2, iy0, ix0, t, tr[0], wr[0]);
            c2_ldg(src, w2, 2 * p + 3, iy0, ix0, t, tr[1], wr[1]);
        }

        #pragma unroll
        for (int ici = 0; ici < 2; ici++) {
            const float* tl = tile[cur][ici];
            const float* wl = wsm[cur][ici];
            #pragma unroll
            for (int r = 0; r < 3; r++)
                #pragma unroll
                for (int s = 0; s < 3; s++) {
                    int k = r * 3 + s;
                    ull W[8];
                    #pragma unroll
                    for (int jp = 0; jp < 8; jp++)
                        W[jp] = *(const ull*)&wl[k * 64 + oc0 + jp * 2];
                    #pragma unroll
                    for (int aa = 0; aa < 2; aa++)
                        #pragma unroll
                        for (int bb2_ = 0; bb2_ < 2; bb2_++) {
                            float v = tl[((py + 8 * aa) * 2 + r) * 33 + (px + 8 * bb2_) * 2 + s];
                            ull vv = packff(v, v);
                            int a = aa * 2 + bb2_;
                            #pragma unroll
                            for (int jp = 0; jp < 8; jp++)
                                acc[a][jp] = fma2(vv, W[jp], acc[a][jp]);
                        }
                }
        }

        if (p < 15) {
            c2_sts(tile[cur ^ 1][0], wsm[cur ^ 1][0], t, tr[0], wr[0]);
            c2_sts(tile[cur ^ 1][1], wsm[cur ^ 1][1], t, tr[1], wr[1]);
        }
        __syncthreads();
    }

    #pragma unroll
    for (int aa = 0; aa < 2; aa++)
        #pragma unroll
        for (int bb2_ = 0; bb2_ < 2; bb2_++) {
            int oy = oy0 + py + 8 * aa;
            int ox = ox0 + px + 8 * bb2_;
            int a = aa * 2 + bb2_;
            #pragma unroll
            for (int jp = 0; jp < 8; jp++) {
                float2 f = unpack2(acc[a][jp]);
                dst[((size_t)(oc0 + jp * 2)     * 128 + oy) * 128 + ox] = fmaxf(f.x, 0.f);
                dst[((size_t)(oc0 + jp * 2 + 1) * 128 + oy) * 128 + ox] = fmaxf(f.y, 0.f);
            }
        }
}

// ---------------- conv3: 64->128, out 64x64, s2, p1, ReLU, 2-ic double-buffered ----------------
__device__ __forceinline__ void c3_ldg(const float* __restrict__ src,
                                       const float* __restrict__ w3,
                                       int ic, int iy0, int ix0, int t,
                                       float tr[3], float wr[5]) {
    #pragma unroll
    for (int u = 0; u < 3; u++) {
        int i = t + u * 256;
        if (i < 561) {
            int ry = i / 33, rx = i % 33;
            int iy = iy0 + ry, ix = ix0 + rx;
            tr[u] = (iy >= 0 && iy < 128 && ix >= 0 && ix < 128)
                    ? src[((size_t)ic * 128 + iy) * 128 + ix] : 0.f;
        }
    }
    #pragma unroll
    for (int u = 0; u < 5; u++) {
        int i = t + u * 256;
        if (i < 1152) {
            int k = i >> 7, oc = i & 127;
            wr[u] = w3[(size_t)oc * 576 + (size_t)ic * 9 + k];
        }
    }
}
__device__ __forceinline__ void c3_sts(float* tb, float* wb, int t,
                                       const float tr[3], const float wr[5]) {
    #pragma unroll
    for (int u = 0; u < 3; u++) { int i = t + u * 256; if (i < 561)  tb[i] = tr[u]; }
    #pragma unroll
    for (int u = 0; u < 5; u++) { int i = t + u * 256; if (i < 1152) wb[i] = wr[u]; }
}

__global__ void __launch_bounds__(256, 2)
conv3_kernel(const float* __restrict__ w3, const float* __restrict__ b3,
             float* __restrict__ out_all) {
    __shared__ __align__(16) float wsm[2][2][1152];
    __shared__ __align__(16) float tile[2][2][561 + 3];
    int t = threadIdx.x;
    int img = blockIdx.z >> 5, b = blockIdx.z & 31;
    const float* src = g_c2 + (size_t)img * C2_PER + (size_t)b * 64 * 128 * 128;
    float* dst = out_all + (img == 0 ? OFF_ZT : OFF_ZT1) + (size_t)b * 128 * 64 * 64;

    int oy0 = blockIdx.y * 8, ox0 = blockIdx.x * 16;
    int iy0 = oy0 * 2 - 1, ix0 = ox0 * 2 - 1;

    int ocs = t >> 5;
    int ps  = t & 31;
    int py  = ps >> 2, px = ps & 3;
    int oc0 = ocs * 16;

    ull acc[4][8];
    #pragma unroll
    for (int jp = 0; jp < 8; jp++) {
        ull bb = packff(b3[oc0 + jp * 2], b3[oc0 + jp * 2 + 1]);
        #pragma unroll
        for (int a = 0; a < 4; a++) acc[a][jp] = bb;
    }

    {
        float tr[2][3], wr[2][5];
        c3_ldg(src, w3, 0, iy0, ix0, t, tr[0], wr[0]);
        c3_ldg(src, w3, 1, iy0, ix0, t, tr[1], wr[1]);
        c3_sts(tile[0][0], wsm[0][0], t, tr[0], wr[0]);
        c3_sts(tile[0][1], wsm[0][1], t, tr[1], wr[1]);
    }
    __syncthreads();

    for (int p = 0; p < 32; p++) {          // 32 stages x 2 ic
        int cur = p & 1;
        float tr[2][3], wr[2][5];
        if (p < 31) {
            c3_ldg(src, w3, 2 * p + 2, iy0, ix0, t, tr[0], wr[0]);
            c3_ldg(src, w3, 2 * p + 3, iy0, ix0, t, tr[1], wr[1]);
        }

        #pragma unroll
        for (int ici = 0; ici < 2; ici++) {
            const float* tl = tile[cur][ici];
            const float* wl = wsm[cur][ici];
            #pragma unroll
            for (int r = 0; r < 3; r++)
                #pragma unroll
                for (int s = 0; s < 3; s++) {
                    int k = r * 3 + s;
                    ull W[8];
                    #pragma unroll
                    for (int jp = 0; jp < 8; jp++)
                        W[jp] = *(const ull*)&wl[k * 128 + oc0 + jp * 2];
                    #pragma unroll
                    for (int bb3 = 0; bb3 < 4; bb3++) {
                        float v = tl[(py * 2 + r) * 33 + (px + 4 * bb3) * 2 + s];
                        ull vv = packff(v, v);
                        #pragma unroll
                        for (int jp = 0; jp < 8; jp++)
                            acc[bb3][jp] = fma2(vv, W[jp], acc[bb3][jp]);
                    }
                }
        }

        if (p < 31) {
            c3_sts(tile[cur ^ 1][0], wsm[cur ^ 1][0], t, tr[0], wr[0]);
            c3_sts(tile[cur ^ 1][1], wsm[cur ^ 1][1], t, tr[1], wr[1]);
        }
        __syncthreads();
    }

    int oy = oy0 + py;
    #pragma unroll
    for (int bb3 = 0; bb3 < 4; bb3++) {
        int ox = ox0 + px + 4 * bb3;
        #pragma unroll
        for (int jp = 0; jp < 8; jp++) {
            float2 f = unpack2(acc[bb3][jp]);
            dst[((size_t)(oc0 + jp * 2)     * 64 + oy) * 64 + ox] = fmaxf(f.x, 0.f);
            dst[((size_t)(oc0 + jp * 2 + 1) * 64 + oy) * 64 + ox] = fmaxf(f.y, 0.f);
        }
    }
}

// ---------------- corr: di-split halves, 2 CTAs/SM ----------------
__global__ void __launch_bounds__(256, 2)
corr_kernel(float* __restrict__ out_all) {
    extern __shared__ __align__(16) float sm[];
    int t = threadIdx.x;
    int half = blockIdx.z & 1;
    int b    = blockIdx.z >> 1;
    int di_lo = half ? 7 : 0;
    int ndi   = half ? 6 : 7;
    int nrows = ndi + 15;
    int rowsz = nrows * 28;

    float* accs = sm;                // [ndi*13][256]
    float* z1t  = sm + ndi * 13 * 256;

    int gy0 = blockIdx.y * 16, gx0 = blockIdx.x * 16;
    const float* zt  = out_all + OFF_ZT  + (size_t)b * 128 * 4096;
    const float* zt1 = out_all + OFF_ZT1 + (size_t)b * 128 * 4096;

    for (int i = t; i < ndi * 13 * 256; i += 256) accs[i] = 0.f;

    int g   = t & 63;
    int tdi = t >> 6;
    int ty  = g >> 2;
    int gx4 = (g & 3) << 2;
    int d0 = tdi, d1 = tdi + 4;
    int nd = (d1 < ndi) ? 2 : ((d0 < ndi) ? 1 : 0);

    for (int cc = 0; cc < 16; cc++) {
        __syncthreads();
        for (int c = 0; c < 8; c++) {
            const float* zsrc = zt1 + ((size_t)(cc * 8 + c)) * 4096;
            float* zd = z1t + c * rowsz;
            #pragma unroll
            for (int u = 0; u < 3; u++) {
                int i = t + u * 256;
                if (i < rowsz) {
                    int yy = i / 28, xx = i - yy * 28;
                    int gy = gy0 - 6 + di_lo + yy, gx = gx0 - 6 + xx;
                    zd[i] = (gy >= 0 && gy < 64 && gx >= 0 && gx < 64)
                            ? zsrc[gy * 64 + gx] : 0.f;
                }
            }
        }
        __syncthreads();

        for (int dd = 0; dd < nd; dd++) {
            int dl = (dd == 0) ? d0 : d1;
            float p[13][4];
            #pragma unroll
            for (int dj = 0; dj < 13; dj++)
                #pragma unroll
                for (int q = 0; q < 4; q++) p[dj][q] = 0.f;

            #pragma unroll
            for (int c = 0; c < 8; c++) {
                float4 z4 = *(const float4*)&zt[((size_t)(cc * 8 + c)) * 4096 +
                                                (gy0 + ty) * 64 + gx0 + gx4];
                const float* rb = &z1t[c * rowsz + (ty + dl) * 28 + gx4];
                float4 r0 = *(const float4*)(rb);
                float4 r1 = *(const float4*)(rb + 4);
                float4 r2 = *(const float4*)(rb + 8);
                float4 r3 = *(const float4*)(rb + 12);
                float rv[16] = {r0.x, r0.y, r0.z, r0.w, r1.x, r1.y, r1.z, r1.w,
                                r2.x, r2.y, r2.z, r2.w, r3.x, r3.y, r3.z, r3.w};
                #pragma unroll
                for (int dj = 0; dj < 13; dj++) {
                    p[dj][0] += z4.x * rv[dj];
                    p[dj][1] += z4.y * rv[dj + 1];
                    p[dj][2] += z4.z * rv[dj + 2];
                    p[dj][3] += z4.w * rv[dj + 3];
                }
            }
            #pragma unroll
            for (int dj = 0; dj < 13; dj++) {
                float4* ap = (float4*)&accs[(dl * 13 + dj) * 256 + g * 4];
                float4 av = *ap;
                av.x += p[dj][0]; av.y += p[dj][1];
                av.z += p[dj][2]; av.w += p[dj][3];
                *ap = av;
            }
        }
    }
    __syncthreads();

    const float inv = 0.0883883476483184f;   // 1/sqrt(128)
    float* co = out_all + OFF_CORR + (size_t)b * 169 * 4096;
    int gy = gy0 + (t >> 4), gx = gx0 + (t & 15);
    for (int o = 0; o < ndi * 13; o++)
        co[(size_t)(di_lo * 13 + o) * 4096 + gy * 64 + gx] = accs[o * 256 + t] * inv;
}

// ---------------- h_t: spatial mean of corr ----------------
__global__ void ht_kernel(float* __restrict__ out_all) {
    int o = blockIdx.x, b = blockIdx.y;
    const float4* co = (const float4*)(out_all + OFF_CORR + ((size_t)b * 169 + o) * 4096);
    float s = 0.f;
    for (int i = threadIdx.x; i < 1024; i += 256) {
        float4 v = co[i];
        s += (v.x + v.y) + (v.z + v.w);
    }
    __shared__ float red[8];
    #pragma unroll
    for (int off = 16; off; off >>= 1) s += __shfl_down_sync(0xffffffffu, s, off);
    if ((threadIdx.x & 31) == 0) red[threadIdx.x >> 5] = s;
    __syncthreads();
    if (threadIdx.x < 8) {
        s = red[threadIdx.x];
        #pragma unroll
        for (int off = 4; off; off >>= 1) s += __shfl_down_sync(0xffu, s, off);
        if (threadIdx.x == 0) out_all[OFF_HT + b * 169 + o] = s * (1.f / 4096.f);
    }
}

// ---------------- head ----------------
__global__ void head_kernel(float* __restrict__ out_all,
                            const float* __restrict__ wh,
                            const float* __restrict__ bh) {
    int t = threadIdx.x;
    if (t >= 64) return;
    int b = t >> 1, j = t & 1;
    const float* h = out_all + OFF_HT + b * 169;
    float s = bh[j];
    for (int o = 0; o < 169; o++) s += h[o] * wh[j * 169 + o];
    out_all[OFF_PRED + b * 2 + j] = s;
}

// ---------------- launch ----------------
extern "C" void kernel_launch(void* const* d_in, const int* in_sizes, int n_in,
                              void* d_out, int out_size) {
    const float* img_t  = (const float*)d_in[0];
    const float* img_t1 = (const float*)d_in[1];
    const float* w1 = (const float*)d_in[2];
    const float* b1 = (const float*)d_in[3];
    const float* w2 = (const float*)d_in[4];
    const float* b2 = (const float*)d_in[5];
    const float* w3 = (const float*)d_in[6];
    const float* b3 = (const float*)d_in[7];
    const float* wh = (const float*)d_in[8];
    const float* bh = (const float*)d_in[9];
    float* out = (float*)d_out;

    conv1_kernel<<<dim3(8, 16, 64), dim3(16, 16)>>>(img_t, img_t1, w1, b1);
    conv2_kernel<<<dim3(8, 8, 64), 256>>>(w2, b2);
    conv3_kernel<<<dim3(4, 8, 64), 256>>>(w3, b3, out);

    int corr_smem = (91 * 256 + 8 * 22 * 28) * 4;   // 112,896 B (half0 max)
    cudaFuncSetAttribute(corr_kernel, cudaFuncAttributeMaxDynamicSharedMemorySize, corr_smem);
    corr_kernel<<<dim3(4, 4, 64), 256, corr_smem>>>(out);

    ht_kernel<<<dim3(169, 32), 256>>>(out);
    head_kernel<<<1, 64>>>(out, wh, bh);
}